// round 16
// baseline (speedup 1.0000x reference)
#include <cuda_runtime.h>
#include <cuda_bf16.h>
#include <cstdint>

// Problem constants (fixed by the reference)
constexpr int B_   = 32;
constexpr int C_   = 3;
constexpr int H_   = 512;
constexpr int W_   = 512;
constexpr int OH_  = 128;
constexpr int OW_  = 64;
constexpr int NNZ_ = 98304;

constexpr int HW_   = H_ * W_;          // 262144
constexpr int CHW_  = C_ * HW_;         // 786432  (per-sample x stride)
constexpr int OHW_  = OH_ * OW_;        // 8192
constexpr int COHW_ = C_ * OHW_;        // 24576   (per-sample out stride)
constexpr int RES_  = B_ * COHW_;       // 786432  (result element count)

constexpr int TPB   = 128;
constexpr int EPT   = 4;
constexpr int GRIDX = NNZ_ / (TPB * EPT);         // 192 CTAs per sample

// ---- cache-policy helpers ----
__device__ __forceinline__ uint64_t make_policy_keep() {
    uint64_t pol;
    asm("createpolicy.fractional.L2::evict_last.b64 %0, 1.0;" : "=l"(pol));
    return pol;
}
__device__ __forceinline__ uint64_t make_policy_stream() {
    uint64_t pol;
    asm("createpolicy.fractional.L2::evict_first.b64 %0, 1.0;" : "=l"(pol));
    return pol;
}
__device__ __forceinline__ float ldg_hint(const float* p, uint64_t pol) {
    float v;
    asm volatile("ld.global.nc.L2::cache_hint.f32 %0, [%1], %2;"
                 : "=f"(v) : "l"(p), "l"(pol));
    return v;
}
__device__ __forceinline__ int4 ldg_hint_i4(const int* p, uint64_t pol) {
    int4 v;
    asm volatile("ld.global.nc.L2::cache_hint.v4.s32 {%0,%1,%2,%3}, [%4], %5;"
                 : "=r"(v.x), "=r"(v.y), "=r"(v.z), "=r"(v.w) : "l"(p), "l"(pol));
    return v;
}
__device__ __forceinline__ float4 ldg_hint_f4(const float* p, uint64_t pol) {
    float4 v;
    asm volatile("ld.global.nc.L2::cache_hint.v4.f32 {%0,%1,%2,%3}, [%4], %5;"
                 : "=f"(v.x), "=f"(v.y), "=f"(v.z), "=f"(v.w) : "l"(p), "l"(pol));
    return v;
}
// No-return global reduction with evict_last policy: output lines are touched
// ~4x each within a sample's time window — keep them L2-resident.
__device__ __forceinline__ void red_add_hint(float* p, float v, uint64_t pol) {
    asm volatile("red.global.L2::cache_hint.add.f32 [%0], %1, %2;"
                 :: "l"(p), "f"(v), "l"(pol) : "memory");
}

__global__ void __launch_bounds__(TPB)
tti_fused_kernel(const float* __restrict__ x,
                 const int*   __restrict__ rows,
                 const int*   __restrict__ cols,
                 const float* __restrict__ vals,
                 const float* __restrict__ mask,
                 float*       __restrict__ out,
                 int mask_elems)
{
    const int b = blockIdx.y;

    if (b == B_) {
        // ---- mask pass-through plane (rasterizes last: overlaps the
        //      scatter ramp-down, not its critical first waves) ----
        const uint64_t pstream = make_policy_stream();
        float4* __restrict__ o4 = reinterpret_cast<float4*>(out + RES_);
        const int total4 = mask_elems >> 2;
        const int stride = GRIDX * TPB;
        for (int i = blockIdx.x * TPB + threadIdx.x; i < total4; i += stride)
            o4[i] = ldg_hint_f4(mask + 4 * i, pstream);
        return;
    }

    // ---- scatter plane (empirical optimum: TPB=128, EPT=4, int4 loads) ----
    const uint64_t pstream = make_policy_stream();
    const uint64_t pkeep   = make_policy_keep();

    const int  k    = (blockIdx.x * TPB + threadIdx.x) * EPT;
    const long base = (long)b * NNZ_ + k;

    const int4   c4 = ldg_hint_i4(cols + base, pstream);
    const int4   r4 = ldg_hint_i4(rows + base, pstream);
    const float4 v4 = ldg_hint_f4(vals + base, pstream);

    const float* __restrict__ xb = x + (long)b * CHW_;
    float*       __restrict__ ob = out + (long)b * COHW_;

    const int   cc[EPT] = {c4.x, c4.y, c4.z, c4.w};
    const int   rr[EPT] = {r4.x, r4.y, r4.z, r4.w};
    const float vv[EPT] = {v4.x, v4.y, v4.z, v4.w};

    // Issue all gathers before any atomic (MLP=4); x sectors evict-last.
    float g[EPT];
#pragma unroll
    for (int i = 0; i < EPT; ++i) {
        const int col = cc[i];
        const int hw  = col / 3;            // spatial index (h*W + w)
        const int ch  = col - 3 * hw;       // channel
        g[i] = ldg_hint(xb + ch * HW_ + hw, pkeep);
    }

    // Fire-and-forget RED scatter, output lines pinned evict_last.
#pragma unroll
    for (int i = 0; i < EPT; ++i) {
        const int row = rr[i];
        const int p   = row / 3;            // oh*OW + ow
        const int rc  = row - 3 * p;        // channel
        red_add_hint(ob + rc * OHW_ + p, vv[i] * g[i], pkeep);
    }
}

extern "C" void kernel_launch(void* const* d_in, const int* in_sizes, int n_in,
                              void* d_out, int out_size)
{
    const float* x    = (const float*)d_in[0];
    const int*   rows = (const int*)  d_in[1];
    const int*   cols = (const int*)  d_in[2];
    const float* vals = (const float*)d_in[3];
    const float* mask = (const float*)d_in[4];
    float* out = (float*)d_out;

    // Node 1: zero the result region (atomics accumulate; out is poisoned).
    cudaMemsetAsync(out, 0, (size_t)RES_ * sizeof(float), 0);

    // Node 2: fused scatter + mask copy.
    const int mask_elems = out_size - RES_;   // = 786432
    dim3 grid(GRIDX, B_ + 1);
    tti_fused_kernel<<<grid, TPB>>>(x, rows, cols, vals, mask, out, mask_elems);
}

// round 17
// speedup vs baseline: 1.0375x; 1.0375x over previous
#include <cuda_runtime.h>
#include <cuda_bf16.h>
#include <cstdint>

// Problem constants (fixed by the reference)
constexpr int B_   = 32;
constexpr int C_   = 3;
constexpr int H_   = 512;
constexpr int W_   = 512;
constexpr int OH_  = 128;
constexpr int OW_  = 64;
constexpr int NNZ_ = 98304;

constexpr int HW_   = H_ * W_;          // 262144
constexpr int CHW_  = C_ * HW_;         // 786432  (per-sample x stride)
constexpr int OHW_  = OH_ * OW_;        // 8192
constexpr int COHW_ = C_ * OHW_;        // 24576   (per-sample out stride)
constexpr int RES_  = B_ * COHW_;       // 786432  (result element count)

constexpr int TPB   = 128;
constexpr int EPT   = 4;
constexpr int GRIDX = NNZ_ / (TPB * EPT);         // 192 CTAs per sample

// ---- cache-policy helpers ----
__device__ __forceinline__ uint64_t make_policy_keep() {
    uint64_t pol;
    asm("createpolicy.fractional.L2::evict_last.b64 %0, 1.0;" : "=l"(pol));
    return pol;
}
__device__ __forceinline__ uint64_t make_policy_stream() {
    uint64_t pol;
    asm("createpolicy.fractional.L2::evict_first.b64 %0, 1.0;" : "=l"(pol));
    return pol;
}
__device__ __forceinline__ float ldg_hint(const float* p, uint64_t pol) {
    float v;
    asm volatile("ld.global.nc.L2::cache_hint.f32 %0, [%1], %2;"
                 : "=f"(v) : "l"(p), "l"(pol));
    return v;
}
__device__ __forceinline__ int4 ldg_hint_i4(const int* p, uint64_t pol) {
    int4 v;
    asm volatile("ld.global.nc.L2::cache_hint.v4.s32 {%0,%1,%2,%3}, [%4], %5;"
                 : "=r"(v.x), "=r"(v.y), "=r"(v.z), "=r"(v.w) : "l"(p), "l"(pol));
    return v;
}
__device__ __forceinline__ float4 ldg_hint_f4(const float* p, uint64_t pol) {
    float4 v;
    asm volatile("ld.global.nc.L2::cache_hint.v4.f32 {%0,%1,%2,%3}, [%4], %5;"
                 : "=f"(v.x), "=f"(v.y), "=f"(v.z), "=f"(v.w) : "l"(p), "l"(pol));
    return v;
}
// No-return global reduction with evict_last policy: output lines are touched
// ~4x each within a sample's time window — keep them L2-resident.
__device__ __forceinline__ void red_add_hint(float* p, float v, uint64_t pol) {
    asm volatile("red.global.L2::cache_hint.add.f32 [%0], %1, %2;"
                 :: "l"(p), "f"(v), "l"(pol) : "memory");
}

__global__ void __launch_bounds__(TPB)
tti_fused_kernel(const float* __restrict__ x,
                 const int*   __restrict__ rows,
                 const int*   __restrict__ cols,
                 const float* __restrict__ vals,
                 const float* __restrict__ mask,
                 float*       __restrict__ out,
                 int mask_elems)
{
    const int b = blockIdx.y;

    if (b == B_) {
        // ---- mask pass-through plane (rasterizes last: overlaps the
        //      scatter ramp-down, not its critical first waves) ----
        const uint64_t pstream = make_policy_stream();
        float4* __restrict__ o4 = reinterpret_cast<float4*>(out + RES_);
        const int total4 = mask_elems >> 2;
        const int stride = GRIDX * TPB;
        for (int i = blockIdx.x * TPB + threadIdx.x; i < total4; i += stride)
            o4[i] = ldg_hint_f4(mask + 4 * i, pstream);
        return;
    }

    // ---- scatter plane (empirical optimum: TPB=128, EPT=4, int4 loads) ----
    const uint64_t pstream = make_policy_stream();
    const uint64_t pkeep   = make_policy_keep();

    const int  k    = (blockIdx.x * TPB + threadIdx.x) * EPT;
    const long base = (long)b * NNZ_ + k;

    const int4   c4 = ldg_hint_i4(cols + base, pstream);
    const int4   r4 = ldg_hint_i4(rows + base, pstream);
    const float4 v4 = ldg_hint_f4(vals + base, pstream);

    const float* __restrict__ xb = x + (long)b * CHW_;
    float*       __restrict__ ob = out + (long)b * COHW_;

    const int   cc[EPT] = {c4.x, c4.y, c4.z, c4.w};
    const int   rr[EPT] = {r4.x, r4.y, r4.z, r4.w};
    const float vv[EPT] = {v4.x, v4.y, v4.z, v4.w};

    // Issue all gathers before any atomic (MLP=4); x sectors evict-last.
    float g[EPT];
#pragma unroll
    for (int i = 0; i < EPT; ++i) {
        const int col = cc[i];
        const int hw  = col / 3;            // spatial index (h*W + w)
        const int ch  = col - 3 * hw;       // channel
        g[i] = ldg_hint(xb + ch * HW_ + hw, pkeep);
    }

    // Fire-and-forget RED scatter, output lines pinned evict_last.
#pragma unroll
    for (int i = 0; i < EPT; ++i) {
        const int row = rr[i];
        const int p   = row / 3;            // oh*OW + ow
        const int rc  = row - 3 * p;        // channel
        red_add_hint(ob + rc * OHW_ + p, vv[i] * g[i], pkeep);
    }
}

extern "C" void kernel_launch(void* const* d_in, const int* in_sizes, int n_in,
                              void* d_out, int out_size)
{
    const float* x    = (const float*)d_in[0];
    const int*   rows = (const int*)  d_in[1];
    const int*   cols = (const int*)  d_in[2];
    const float* vals = (const float*)d_in[3];
    const float* mask = (const float*)d_in[4];
    float* out = (float*)d_out;

    // Node 1: zero the result region (atomics accumulate; out is poisoned).
    cudaMemsetAsync(out, 0, (size_t)RES_ * sizeof(float), 0);

    // Node 2: fused scatter + mask copy.
    const int mask_elems = out_size - RES_;   // = 786432
    dim3 grid(GRIDX, B_ + 1);
    tti_fused_kernel<<<grid, TPB>>>(x, rows, cols, vals, mask, out, mask_elems);
}